// round 11
// baseline (speedup 1.0000x reference)
#include <cuda_runtime.h>
#include <cuda_fp16.h>
#include <cuda_bf16.h>
#include <cstdint>

// Problem constants
#define NN 50000
#define EE 800000
#define KD 256
#define HH 8
#define HC 256
#define RSQRT_C 0.17677669529663687f

// Smem layout (dynamic): double-buffered fp16 staging for A (64x64 chunk) and
// B (64x256 chunk); padded row strides keep ldmatrix conflict-free. After the
// mainloop the same memory is reused as the f32 result tile Es[64][256]
// (XOR-swizzled at float4 granularity).
#define SA 144                 // A row stride bytes (64 fp16 + 8 pad)
#define SB 528                 // B row stride bytes (256 fp16 + 8 pad)
#define A_ST0 0                // 64*144 = 9216
#define A_ST1 9216
#define B_ST0 18432            // 64*528 = 33792
#define B_ST1 52224
#define DYN_BYTES 86016        // staging 84KB >= Es 64KB

// ---------------------------------------------------------------------------
// Scratch (device globals; no allocation allowed)
// ---------------------------------------------------------------------------
__device__ __align__(16) float g_Q[NN * HC];
__device__ __align__(16) float g_K[NN * HC];
__device__ __align__(16) float g_V[NN * HC];
__device__ __align__(16) float g_acc[NN * HC];
__device__ float g_den[NN * HH];
__device__ int   g_idx64;
__device__ int   g_src[EE];
__device__ int   g_dst[EE];
// Per matrix: 65536 fp16, K-major [k][n]
__device__ __align__(16) __half g_Wimg[5 * 65536];

// ---------------------------------------------------------------------------
// Helpers
// ---------------------------------------------------------------------------
__device__ __forceinline__ uint32_t smem_u32(const void* p) {
    uint32_t a;
    asm("{ .reg .u64 t; cvta.to.shared.u64 t, %1; cvt.u32.u64 %0, t; }"
        : "=r"(a) : "l"(p));
    return a;
}
__device__ __forceinline__ void ldsm_x4(uint32_t& r0, uint32_t& r1,
                                        uint32_t& r2, uint32_t& r3, uint32_t a) {
    asm volatile("ldmatrix.sync.aligned.m8n8.x4.shared.b16 {%0,%1,%2,%3}, [%4];"
                 : "=r"(r0), "=r"(r1), "=r"(r2), "=r"(r3) : "r"(a));
}
__device__ __forceinline__ void ldsm_x4t(uint32_t& r0, uint32_t& r1,
                                         uint32_t& r2, uint32_t& r3, uint32_t a) {
    asm volatile("ldmatrix.sync.aligned.m8n8.x4.trans.shared.b16 {%0,%1,%2,%3}, [%4];"
                 : "=r"(r0), "=r"(r1), "=r"(r2), "=r"(r3) : "r"(a));
}
__device__ __forceinline__ void mma16816(float* c, const uint32_t* a,
                                         uint32_t b0, uint32_t b1) {
    asm volatile("mma.sync.aligned.m16n8k16.row.col.f32.f16.f16.f32 "
                 "{%0,%1,%2,%3}, {%4,%5,%6,%7}, {%8,%9}, {%0,%1,%2,%3};"
                 : "+f"(c[0]), "+f"(c[1]), "+f"(c[2]), "+f"(c[3])
                 : "r"(a[0]), "r"(a[1]), "r"(a[2]), "r"(a[3]), "r"(b0), "r"(b1));
}
__device__ __forceinline__ uint32_t hpack(float x, float y) {
    __half2 h = __floats2half2_rn(x, y);
    return *(uint32_t*)&h;
}
__device__ __forceinline__ void cp16(uint32_t dst, const void* src) {
    asm volatile("cp.async.ca.shared.global [%0], [%1], 16;"
                 :: "r"(dst), "l"(src) : "memory");
}
#define CP_COMMIT() asm volatile("cp.async.commit_group;" ::: "memory")
#define CP_WAIT(n)  asm volatile("cp.async.wait_group %0;" :: "n"(n) : "memory")

__device__ __forceinline__ void red_add_v4(float* p, float4 v) {
    asm volatile("red.global.add.v4.f32 [%0], {%1,%2,%3,%4};"
                 :: "l"(p), "f"(v.x), "f"(v.y), "f"(v.z), "f"(v.w)
                 : "memory");
}
// Es (64x256 f32) swizzled addressing: float4 slot s in row r lives at slot s^(r&7)
__device__ __forceinline__ float4 es_ld(const char* dyn, int row, int col) {
    int slot = col >> 2;
    return *(const float4*)(dyn + row * 1024 + ((slot ^ (row & 7)) << 4));
}
__device__ __forceinline__ void es_st8(char* dyn, int row, int col, float c0, float c1) {
    int slot = col >> 2;
    *(float2*)(dyn + row * 1024 + ((slot ^ (row & 7)) << 4) + ((col & 3) << 2))
        = make_float2(c0, c1);
}

// ---------------------------------------------------------------------------
// Prologue kernels
// ---------------------------------------------------------------------------
__global__ void detect_kernel(const int* __restrict__ ei32) {
    if (threadIdx.x == 0) {
        int nz = 0;
#pragma unroll
        for (int i = 0; i < 64; i++) nz |= ei32[2 * i + 1];
        g_idx64 = (nz == 0) ? 1 : 0;
    }
}
__global__ void extract_kernel(const void* __restrict__ ei) {
    int e = blockIdx.x * 256 + threadIdx.x;
    if (e >= EE) return;
    if (g_idx64) {
        const long long* p = (const long long*)ei;
        g_src[e] = (int)p[e];
        g_dst[e] = (int)p[EE + e];
    } else {
        const int* p = (const int*)ei;
        g_src[e] = p[e];
        g_dst[e] = p[EE + e];
    }
}
// W[k][n] -> fp16 image, K-major [k][n]
__global__ void prep_kernel(const float* __restrict__ Wq, const float* __restrict__ Wk,
                            const float* __restrict__ Wv, const float* __restrict__ Ws,
                            const float* __restrict__ We) {
    int id = blockIdx.x * 256 + threadIdx.x;
    if (id >= 5 * 65536) return;
    int mat = id >> 16;
    int rem = id & 65535;
    int k = rem >> 8, n = rem & 255;
    const float* W = (mat == 0) ? Wq : (mat == 1) ? Wk : (mat == 2) ? Wv
                   : (mat == 3) ? Ws : We;
    g_Wimg[(size_t)mat * 65536 + (size_t)k * 256 + n] = __float2half_rn(W[k * HC + n]);
}
__global__ void zero_kernel() {
    int idx = blockIdx.x * 256 + threadIdx.x;
    if (idx < NN * HC) g_acc[idx] = 0.f;
    int base = NN * HC;
    if (idx >= base && idx < base + NN * HH) g_den[idx - base] = 0.f;
}

// ---------------------------------------------------------------------------
// fp16 HMMA GEMM with software pipelining:
// Es[64][256] = A[row0..+63, 0:256] @ B. Block = 256 threads = 8 warps;
// warp w computes all 64 rows of cols [w*32, w*32+32).
// A: fp32->fp16 in-kernel, double-buffered smem, convert of chunk kc+1
//    overlaps mma of chunk kc.
// B: cp.async double-buffered; the wait for B(kc+1) comes AFTER the mma phase.
// One __syncthreads per chunk. Result left in swizzled Es (smem reuse).
// ---------------------------------------------------------------------------
__device__ __forceinline__ void a_convert_store(const float4* ar, char* abuf,
                                                int r, int q) {
    uint4 H0 = make_uint4(hpack(ar[0].x, ar[0].y), hpack(ar[0].z, ar[0].w),
                          hpack(ar[1].x, ar[1].y), hpack(ar[1].z, ar[1].w));
    uint4 H1 = make_uint4(hpack(ar[2].x, ar[2].y), hpack(ar[2].z, ar[2].w),
                          hpack(ar[3].x, ar[3].y), hpack(ar[3].z, ar[3].w));
    char* dh = abuf + r * SA + q * 32;
    *(uint4*)dh = H0; *(uint4*)(dh + 16) = H1;
}
__device__ __forceinline__ void b_issue_cp(const __half* Bg, int kc, uint32_t bSm,
                                           int kr, int p2) {
    uint32_t dst = bSm + kr * SB + p2 * 128;
    const char* src = (const char*)(Bg + (size_t)(kc * 64 + kr) * 256 + p2 * 64);
#pragma unroll
    for (int j = 0; j < 8; j++) cp16(dst + j * 16, src + j * 16);
    CP_COMMIT();
}

__device__ __forceinline__ void gemm_hmma(const float* __restrict__ A, int row0, int maxrow,
                                          const __half* __restrict__ Bg,
                                          char* dyn) {
    const int tid = threadIdx.x;
    const int w = tid >> 5, l = tid & 31;

    float c[4][4][4];
#pragma unroll
    for (int mt = 0; mt < 4; mt++)
#pragma unroll
        for (int nt = 0; nt < 4; nt++)
#pragma unroll
            for (int j = 0; j < 4; j++) c[mt][nt][j] = 0.f;

    const uint32_t aSm0 = smem_u32(dyn + A_ST0);
    const uint32_t aSm1 = smem_u32(dyn + A_ST1);
    const uint32_t bSm0 = smem_u32(dyn + B_ST0);
    const uint32_t bSm1 = smem_u32(dyn + B_ST1);

    // per-thread roles
    const int r = tid >> 2, q = tid & 3;          // A: row, 16-float quarter
    int grow = row0 + r;
    if (grow > maxrow) grow = maxrow;
    const float4* abase = (const float4*)(A + (size_t)grow * KD);
    const int kr = tid >> 2, p2 = tid & 3;        // B: row, 128B piece

    // ldmatrix addressing
    const int lrow = (l & 7) + (l & 8);           // A: 0..15
    const int acol = (l & 16) ? 8 : 0;
    const int brow = l & 15;                      // B x4t: k row within 16
    const int bcoff = (l & 16) ? 8 : 0;           // B x4t: second col-group

    // ---- prologue: B(0) async; A(0) convert+store; A(1) regs
    b_issue_cp(Bg, 0, bSm0, kr, p2);
    float4 ar[4];
#pragma unroll
    for (int j = 0; j < 4; j++) ar[j] = abase[q * 4 + j];
    a_convert_store(ar, dyn + A_ST0, r, q);
#pragma unroll
    for (int j = 0; j < 4; j++) ar[j] = abase[16 + q * 4 + j];
    CP_WAIT(0);
    __syncthreads();

#pragma unroll 1
    for (int kc = 0; kc < 4; ++kc) {
        // prefetch next chunk (overlaps this chunk's mma phase)
        if (kc < 3) {
            b_issue_cp(Bg, kc + 1, ((kc + 1) & 1) ? bSm1 : bSm0, kr, p2);
            a_convert_store(ar, dyn + (((kc + 1) & 1) ? A_ST1 : A_ST0), r, q);
            if (kc < 2) {
#pragma unroll
                for (int j = 0; j < 4; j++) ar[j] = abase[(kc + 2) * 16 + q * 4 + j];
            }
        }
        const uint32_t aSm = (kc & 1) ? aSm1 : aSm0;
        const uint32_t bSm = (kc & 1) ? bSm1 : bSm0;
#pragma unroll
        for (int kk = 0; kk < 4; kk++) {
            uint32_t ah[4][4];
#pragma unroll
            for (int mt = 0; mt < 4; mt++) {
                uint32_t off = (uint32_t)((mt * 16 + lrow) * SA + (kk * 16 + acol) * 2);
                ldsm_x4(ah[mt][0], ah[mt][1], ah[mt][2], ah[mt][3], aSm + off);
            }
            uint32_t bh[4][2];
#pragma unroll
            for (int pr = 0; pr < 2; pr++) {
                uint32_t off = (uint32_t)((kk * 16 + brow) * SB
                                          + (w * 32 + pr * 16 + bcoff) * 2);
                ldsm_x4t(bh[2 * pr][0], bh[2 * pr][1],
                         bh[2 * pr + 1][0], bh[2 * pr + 1][1], bSm + off);
            }
#pragma unroll
            for (int mt = 0; mt < 4; mt++)
#pragma unroll
                for (int nt = 0; nt < 4; nt++)
                    mma16816(c[mt][nt], ah[mt], bh[nt][0], bh[nt][1]);
        }
        if (kc < 3) { CP_WAIT(0); }      // B(kc+1) landed during the mma phase
        __syncthreads();                 // all reads of this chunk done
    }
    // --- scatter fragments into swizzled Es
    const int gid = l >> 2, tig = l & 3;
#pragma unroll
    for (int mt = 0; mt < 4; mt++)
#pragma unroll
        for (int nt = 0; nt < 4; nt++) {
            int row = mt * 16 + gid;
            int col = w * 32 + nt * 8 + tig * 2;
            es_st8(dyn, row,     col, c[mt][nt][0], c[mt][nt][1]);
            es_st8(dyn, row + 8, col, c[mt][nt][2], c[mt][nt][3]);
        }
    __syncthreads();
}

// ---------------------------------------------------------------------------
// Q/K/V/skip projections (blockIdx.y = matrix); skip writes d_out directly.
// ---------------------------------------------------------------------------
__global__ void __launch_bounds__(256, 2)
qkvs_kernel(const float* __restrict__ x,
            const float* __restrict__ bq, const float* __restrict__ bk,
            const float* __restrict__ bv, const float* __restrict__ bs,
            float* __restrict__ dout) {
    extern __shared__ char dyn[];
    const int mat = blockIdx.y;
    const float* bias = (mat == 0) ? bq : (mat == 1) ? bk : (mat == 2) ? bv : bs;
    float* outp = (mat == 0) ? g_Q : (mat == 1) ? g_K : (mat == 2) ? g_V : dout;
    const int row0 = blockIdx.x * 64;

    gemm_hmma(x, row0, NN - 1, g_Wimg + (size_t)mat * 65536, dyn);

    const int tid = threadIdx.x;
    const int te = tid & 7, to = tid >> 3;
    float bb[8];
#pragma unroll
    for (int j = 0; j < 8; j++) bb[j] = bias[to * 8 + j];

#pragma unroll
    for (int i = 0; i < 8; i++) {
        int rl = te * 8 + i;
        int row = row0 + rl;
        if (row < NN) {
            float4 e0 = es_ld(dyn, rl, to * 8);
            float4 e1 = es_ld(dyn, rl, to * 8 + 4);
            float* op = outp + (size_t)row * HC + to * 8;
            *(float4*)op = make_float4(e0.x + bb[0], e0.y + bb[1],
                                       e0.z + bb[2], e0.w + bb[3]);
            *(float4*)(op + 4) = make_float4(e1.x + bb[4], e1.y + bb[5],
                                             e1.z + bb[6], e1.w + bb[7]);
        }
    }
}

// ---------------------------------------------------------------------------
// Edge kernel: e = edge_attr @ We (fp16 HMMA) into Es, then fused attention:
// warp w == head w; per edge the 4 lanes {tl} hold its 32 channels; dot with
// gathered q against (k+e), shfl-reduce, max-free exp, red.v4 scatter.
// ---------------------------------------------------------------------------
__global__ void __launch_bounds__(256, 2)
edge_kernel(const float* __restrict__ ea) {
    extern __shared__ char dyn[];
    __shared__ int s_src[64];
    __shared__ int s_dst[64];

    const int tid = threadIdx.x;
    const int row0 = blockIdx.x * 64;      // EE = 12500 * 64, no tail
    if (tid < 64) {
        s_src[tid] = g_src[row0 + tid];
        s_dst[tid] = g_dst[row0 + tid];
    }
    // visibility guaranteed by syncthreads inside gemm_hmma

    gemm_hmma(ea, row0, EE - 1, g_Wimg + (size_t)4 * 65536, dyn);

    const int w  = tid >> 5;
    const int l  = tid & 31;
    const int te = tid & 7;
    const int tl = l >> 3;
    const int cbase = w * 32 + tl * 8;

#pragma unroll
    for (int i = 0; i < 8; i++) {
        const int eg  = te * 8 + i;
        const int src = s_src[eg];
        const int dst = s_dst[eg];

        float4 e0 = es_ld(dyn, eg, cbase);
        float4 e1 = es_ld(dyn, eg, cbase + 4);

        const float4* qp = (const float4*)(g_Q + (size_t)dst * HC + cbase);
        const float4* kp = (const float4*)(g_K + (size_t)src * HC + cbase);
        float4 q0 = qp[0], q1 = qp[1];
        float4 k0 = kp[0], k1 = kp[1];

        float p = (k0.x + e0.x) * q0.x + (k0.y + e0.y) * q0.y
                + (k0.z + e0.z) * q0.z + (k0.w + e0.w) * q0.w
                + (k1.x + e1.x) * q1.x + (k1.y + e1.y) * q1.y
                + (k1.z + e1.z) * q1.z + (k1.w + e1.w) * q1.w;

        p += __shfl_xor_sync(0xffffffffu, p, 8);
        p += __shfl_xor_sync(0xffffffffu, p, 16);

        float exv = __expf(p * RSQRT_C);

        if (tl == 0) atomicAdd(g_den + (size_t)dst * HH + w, exv);

        const float4* vp = (const float4*)(g_V + (size_t)src * HC + cbase);
        float4 v0 = vp[0], v1 = vp[1];
        float* op = g_acc + (size_t)dst * HC + cbase;
        red_add_v4(op, make_float4(exv * (v0.x + e0.x), exv * (v0.y + e0.y),
                                   exv * (v0.z + e0.z), exv * (v0.w + e0.w)));
        red_add_v4(op + 4, make_float4(exv * (v1.x + e1.x), exv * (v1.y + e1.y),
                                       exv * (v1.z + e1.z), exv * (v1.w + e1.w)));
    }
}

// ---------------------------------------------------------------------------
// Finalize: out += acc / den
// ---------------------------------------------------------------------------
__global__ void finalize_kernel(float* __restrict__ out) {
    int idx = blockIdx.x * 256 + threadIdx.x;
    if (idx < NN * HC) {
        int n = idx >> 8;
        int h = (idx & 255) >> 5;
        float den = g_den[n * HH + h];
        float add = (den > 0.f) ? g_acc[idx] / den : 0.f;
        out[idx] += add;
    }
}

// ---------------------------------------------------------------------------
// Launch
// ---------------------------------------------------------------------------
extern "C" void kernel_launch(void* const* d_in, const int* in_sizes, int n_in,
                              void* d_out, int out_size) {
    (void)in_sizes; (void)n_in; (void)out_size;
    const float* x  = (const float*)d_in[0];
    const void*  ei = d_in[1];
    const float* ea = (const float*)d_in[2];
    const float* Wq = (const float*)d_in[3];
    const float* bq = (const float*)d_in[4];
    const float* Wk = (const float*)d_in[5];
    const float* bk = (const float*)d_in[6];
    const float* Wv = (const float*)d_in[7];
    const float* bv = (const float*)d_in[8];
    const float* We = (const float*)d_in[9];
    const float* Ws = (const float*)d_in[10];
    const float* bs = (const float*)d_in[11];
    float* out = (float*)d_out;

    cudaFuncSetAttribute(qkvs_kernel, cudaFuncAttributeMaxDynamicSharedMemorySize, DYN_BYTES);
    cudaFuncSetAttribute(edge_kernel, cudaFuncAttributeMaxDynamicSharedMemorySize, DYN_BYTES);

    detect_kernel<<<1, 32>>>((const int*)ei);
    extract_kernel<<<(EE + 255) / 256, 256>>>(ei);
    prep_kernel<<<(5 * 65536 + 255) / 256, 256>>>(Wq, Wk, Wv, Ws, We);
    {
        int total = NN * HC + NN * HH;
        zero_kernel<<<(total + 255) / 256, 256>>>();
    }
    {
        dim3 grid((NN + 63) / 64, 4);
        qkvs_kernel<<<grid, 256, DYN_BYTES>>>(x, bq, bk, bv, bs, out);
    }
    edge_kernel<<<EE / 64, 256, DYN_BYTES>>>(ea);
    finalize_kernel<<<(NN * HC + 255) / 256, 256>>>(out);
}

// round 15
// speedup vs baseline: 1.1786x; 1.1786x over previous
#include <cuda_runtime.h>
#include <cuda_fp16.h>
#include <cuda_bf16.h>
#include <cstdint>

// Problem constants
#define NN 50000
#define EE 800000
#define KD 256
#define HH 8
#define HC 256
#define RSQRT_C 0.17677669529663687f

// Smem layout (dynamic): fp16 staging for A (64x64 chunk) and double-buffered
// B (64x256 chunk x2); padded row strides keep ldmatrix conflict-free. After
// the mainloop the same memory is reused as the f32 result tile Es[64][256]
// (XOR-swizzled at float4 granularity).
#define SA 144                 // A row stride bytes (64 fp16 + 8 pad)
#define SB 528                 // B row stride bytes (256 fp16 + 8 pad)
#define A_ST 0                 // 64*144 = 9216
#define B_ST0 9216             // 64*528 = 33792
#define B_ST1 43008
#define DYN_BYTES 76800        // staging 75KB >= Es 64KB

// ---------------------------------------------------------------------------
// Scratch (device globals; no allocation allowed)
// ---------------------------------------------------------------------------
__device__ __align__(16) float g_Q[NN * HC];
__device__ __align__(16) float g_K[NN * HC];
__device__ __align__(16) float g_V[NN * HC];
__device__ __align__(16) float g_acc[NN * HC];
__device__ float g_den[NN * HH];
__device__ int   g_idx64;
__device__ int   g_src[EE];
__device__ int   g_dst[EE];
// dst-sort scratch
__device__ int   g_hist[NN];          // counts -> exclusive offsets -> bump ptrs
__device__ int   g_perm[EE];          // sorted position -> original edge id
__device__ int   g_src_s[EE];
__device__ int   g_dst_s[EE];
// Per matrix: 65536 fp16, K-major [k][n]
__device__ __align__(16) __half g_Wimg[5 * 65536];

// ---------------------------------------------------------------------------
// Helpers
// ---------------------------------------------------------------------------
__device__ __forceinline__ uint32_t smem_u32(const void* p) {
    uint32_t a;
    asm("{ .reg .u64 t; cvta.to.shared.u64 t, %1; cvt.u32.u64 %0, t; }"
        : "=r"(a) : "l"(p));
    return a;
}
__device__ __forceinline__ void ldsm_x4(uint32_t& r0, uint32_t& r1,
                                        uint32_t& r2, uint32_t& r3, uint32_t a) {
    asm volatile("ldmatrix.sync.aligned.m8n8.x4.shared.b16 {%0,%1,%2,%3}, [%4];"
                 : "=r"(r0), "=r"(r1), "=r"(r2), "=r"(r3) : "r"(a));
}
__device__ __forceinline__ void ldsm_x2t(uint32_t& r0, uint32_t& r1, uint32_t a) {
    asm volatile("ldmatrix.sync.aligned.m8n8.x2.trans.shared.b16 {%0,%1}, [%2];"
                 : "=r"(r0), "=r"(r1) : "r"(a));
}
__device__ __forceinline__ void mma16816(float* c, const uint32_t* a,
                                         uint32_t b0, uint32_t b1) {
    asm volatile("mma.sync.aligned.m16n8k16.row.col.f32.f16.f16.f32 "
                 "{%0,%1,%2,%3}, {%4,%5,%6,%7}, {%8,%9}, {%0,%1,%2,%3};"
                 : "+f"(c[0]), "+f"(c[1]), "+f"(c[2]), "+f"(c[3])
                 : "r"(a[0]), "r"(a[1]), "r"(a[2]), "r"(a[3]), "r"(b0), "r"(b1));
}
__device__ __forceinline__ uint32_t hpack(float x, float y) {
    __half2 h = __floats2half2_rn(x, y);
    return *(uint32_t*)&h;
}
__device__ __forceinline__ void cp16(uint32_t dst, const void* src) {
    asm volatile("cp.async.ca.shared.global [%0], [%1], 16;"
                 :: "r"(dst), "l"(src) : "memory");
}
#define CP_COMMIT() asm volatile("cp.async.commit_group;" ::: "memory")
#define CP_WAIT(n)  asm volatile("cp.async.wait_group %0;" :: "n"(n) : "memory")

__device__ __forceinline__ void red_add_v4(float* p, float4 v) {
    asm volatile("red.global.add.v4.f32 [%0], {%1,%2,%3,%4};"
                 :: "l"(p), "f"(v.x), "f"(v.y), "f"(v.z), "f"(v.w)
                 : "memory");
}
// Es (64x256 f32) swizzled addressing: float4 slot s in row r lives at slot s^(r&7)
__device__ __forceinline__ float4 es_ld(const char* dyn, int row, int col) {
    int slot = col >> 2;
    return *(const float4*)(dyn + row * 1024 + ((slot ^ (row & 7)) << 4));
}
__device__ __forceinline__ void es_st8(char* dyn, int row, int col, float c0, float c1) {
    int slot = col >> 2;
    *(float2*)(dyn + row * 1024 + ((slot ^ (row & 7)) << 4) + ((col & 3) << 2))
        = make_float2(c0, c1);
}

// ---------------------------------------------------------------------------
// Prologue kernels
// ---------------------------------------------------------------------------
__global__ void detect_kernel(const int* __restrict__ ei32) {
    if (threadIdx.x == 0) {
        int nz = 0;
#pragma unroll
        for (int i = 0; i < 64; i++) nz |= ei32[2 * i + 1];
        g_idx64 = (nz == 0) ? 1 : 0;
    }
}
__global__ void extract_kernel(const void* __restrict__ ei) {
    int e = blockIdx.x * 256 + threadIdx.x;
    if (e >= EE) return;
    if (g_idx64) {
        const long long* p = (const long long*)ei;
        g_src[e] = (int)p[e];
        g_dst[e] = (int)p[EE + e];
    } else {
        const int* p = (const int*)ei;
        g_src[e] = p[e];
        g_dst[e] = p[EE + e];
    }
}
// W[k][n] -> fp16 image, K-major [k][n]
__global__ void prep_kernel(const float* __restrict__ Wq, const float* __restrict__ Wk,
                            const float* __restrict__ Wv, const float* __restrict__ Ws,
                            const float* __restrict__ We) {
    int id = blockIdx.x * 256 + threadIdx.x;
    if (id >= 5 * 65536) return;
    int mat = id >> 16;
    int rem = id & 65535;
    int k = rem >> 8, n = rem & 255;
    const float* W = (mat == 0) ? Wq : (mat == 1) ? Wk : (mat == 2) ? Wv
                   : (mat == 3) ? Ws : We;
    g_Wimg[(size_t)mat * 65536 + (size_t)k * 256 + n] = __float2half_rn(W[k * HC + n]);
}
__global__ void zero_kernel() {
    int idx = blockIdx.x * 256 + threadIdx.x;
    if (idx < NN * HC) g_acc[idx] = 0.f;
    int b1 = NN * HC;
    if (idx >= b1 && idx < b1 + NN * HH) g_den[idx - b1] = 0.f;
    int b2 = b1 + NN * HH;
    if (idx >= b2 && idx < b2 + NN) g_hist[idx - b2] = 0;
}
// --- counting sort by dst ---
__global__ void hist_kernel() {
    int e = blockIdx.x * 256 + threadIdx.x;
    if (e < EE) atomicAdd(&g_hist[g_dst[e]], 1);
}
__global__ void scan_kernel() {      // single block, 1024 threads
    __shared__ int part[1024];
    const int t = threadIdx.x;
    const int PER = (NN + 1023) / 1024;   // 49
    int s = 0;
    for (int i = 0; i < PER; i++) {
        int idx = t * PER + i;
        if (idx < NN) s += g_hist[idx];
    }
    part[t] = s;
    __syncthreads();
    for (int off = 1; off < 1024; off <<= 1) {
        int v = (t >= off) ? part[t - off] : 0;
        __syncthreads();
        part[t] += v;
        __syncthreads();
    }
    int run = (t == 0) ? 0 : part[t - 1];
    for (int i = 0; i < PER; i++) {
        int idx = t * PER + i;
        if (idx < NN) {
            int c = g_hist[idx];
            g_hist[idx] = run;
            run += c;
        }
    }
}
__global__ void scatter_kernel() {
    int e = blockIdx.x * 256 + threadIdx.x;
    if (e >= EE) return;
    int d = g_dst[e];
    int pos = atomicAdd(&g_hist[d], 1);
    g_perm[pos] = e;
    g_dst_s[pos] = d;
    g_src_s[pos] = g_src[e];
}

// ---------------------------------------------------------------------------
// HMMA GEMM (fp16): Es[64][256] = A[rows, 0:256] @ B. Block = 256 threads =
// 8 warps; warp w computes all 64 rows of cols [w*32, w*32+32). B double-
// buffered via cp.async; A fp32->fp16 converted in-kernel with one-chunk
// register prefetch. Rows optionally indirected through perm (edge gather).
// Result left in swizzled Es.
// ---------------------------------------------------------------------------
__device__ __forceinline__ void gemm_hmma(const float* __restrict__ A, int row0, int maxrow,
                                          const int* __restrict__ perm,
                                          const __half* __restrict__ Bg,
                                          char* dyn) {
    const int tid = threadIdx.x;
    const int w = tid >> 5, l = tid & 31;

    float c[4][4][4];
#pragma unroll
    for (int mt = 0; mt < 4; mt++)
#pragma unroll
        for (int nt = 0; nt < 4; nt++)
#pragma unroll
            for (int j = 0; j < 4; j++) c[mt][nt][j] = 0.f;

    const uint32_t aSm = smem_u32(dyn + A_ST);
    const uint32_t bSm0 = smem_u32(dyn + B_ST0);
    const uint32_t bSm1 = smem_u32(dyn + B_ST1);

    // per-thread roles
    const int r = tid >> 2, q = tid & 3;          // A: row, 16-float quarter
    int trow = row0 + r;
    if (trow > maxrow) trow = maxrow;
    const int grow = perm ? perm[trow] : trow;
    const float4* abase = (const float4*)(A + (size_t)grow * KD);
    const int kr = tid >> 2, p2 = tid & 3;        // B: row, 128B piece

    // ldmatrix lane-row components
    const int lrow = (l & 7) + (l & 8);           // 0..15
    const int acol = (l & 16) ? 8 : 0;

    // ---- prologue: B(0) async, A(0) regs
    {
        uint32_t dst = bSm0 + kr * SB + p2 * 128;
        const char* src = (const char*)(Bg + (size_t)kr * 256 + p2 * 64);
#pragma unroll
        for (int j = 0; j < 8; j++) cp16(dst + j * 16, src + j * 16);
        CP_COMMIT();
    }
    float4 ar[4];
#pragma unroll
    for (int j = 0; j < 4; j++) ar[j] = abase[q * 4 + j];

#pragma unroll 1
    for (int kc = 0; kc < 4; kc++) {
        // prefetch B(kc+1)
        if (kc < 3) {
            uint32_t dst = ((kc + 1) & 1 ? bSm1 : bSm0) + kr * SB + p2 * 128;
            const char* src = (const char*)(Bg + (size_t)((kc + 1) * 64 + kr) * 256 + p2 * 64);
#pragma unroll
            for (int j = 0; j < 8; j++) cp16(dst + j * 16, src + j * 16);
            CP_COMMIT();
        }
        // convert+store A(kc) from regs
        {
            uint4 H0 = make_uint4(hpack(ar[0].x, ar[0].y), hpack(ar[0].z, ar[0].w),
                                  hpack(ar[1].x, ar[1].y), hpack(ar[1].z, ar[1].w));
            uint4 H1 = make_uint4(hpack(ar[2].x, ar[2].y), hpack(ar[2].z, ar[2].w),
                                  hpack(ar[3].x, ar[3].y), hpack(ar[3].z, ar[3].w));
            char* dh = dyn + A_ST + r * SA + q * 32;
            *(uint4*)dh = H0; *(uint4*)(dh + 16) = H1;
        }
        // issue A(kc+1) global loads (consumed next iteration)
        if (kc < 3) {
#pragma unroll
            for (int j = 0; j < 4; j++) ar[j] = abase[(kc + 1) * 16 + q * 4 + j];
        }
        if (kc < 3) { CP_WAIT(1); } else { CP_WAIT(0); }
        __syncthreads();

        const uint32_t bSm = (kc & 1) ? bSm1 : bSm0;
#pragma unroll
        for (int kk = 0; kk < 4; kk++) {
            uint32_t ah[4][4];
#pragma unroll
            for (int mt = 0; mt < 4; mt++) {
                uint32_t off = (uint32_t)((mt * 16 + lrow) * SA + (kk * 16 + acol) * 2);
                ldsm_x4(ah[mt][0], ah[mt][1], ah[mt][2], ah[mt][3], aSm + off);
            }
            uint32_t bh[4][2];
#pragma unroll
            for (int nt = 0; nt < 4; nt++) {
                uint32_t off = (uint32_t)((kk * 16 + lrow) * SB + (w * 32 + nt * 8) * 2);
                ldsm_x2t(bh[nt][0], bh[nt][1], bSm + off);
            }
#pragma unroll
            for (int mt = 0; mt < 4; mt++)
#pragma unroll
                for (int nt = 0; nt < 4; nt++)
                    mma16816(c[mt][nt], ah[mt], bh[nt][0], bh[nt][1]);
        }
        __syncthreads();                 // all reads done before next A store / Es reuse
    }
    // --- scatter fragments into swizzled Es
    const int gid = l >> 2, tig = l & 3;
#pragma unroll
    for (int mt = 0; mt < 4; mt++)
#pragma unroll
        for (int nt = 0; nt < 4; nt++) {
            int row = mt * 16 + gid;
            int col = w * 32 + nt * 8 + tig * 2;
            es_st8(dyn, row,     col, c[mt][nt][0], c[mt][nt][1]);
            es_st8(dyn, row + 8, col, c[mt][nt][2], c[mt][nt][3]);
        }
    __syncthreads();
}

// ---------------------------------------------------------------------------
// Q/K/V/skip projections (blockIdx.y = matrix); skip writes d_out directly.
// ---------------------------------------------------------------------------
__global__ void __launch_bounds__(256, 2)
qkvs_kernel(const float* __restrict__ x,
            const float* __restrict__ bq, const float* __restrict__ bk,
            const float* __restrict__ bv, const float* __restrict__ bs,
            float* __restrict__ dout) {
    extern __shared__ char dyn[];
    const int mat = blockIdx.y;
    const float* bias = (mat == 0) ? bq : (mat == 1) ? bk : (mat == 2) ? bv : bs;
    float* outp = (mat == 0) ? g_Q : (mat == 1) ? g_K : (mat == 2) ? g_V : dout;
    const int row0 = blockIdx.x * 64;

    gemm_hmma(x, row0, NN - 1, nullptr, g_Wimg + (size_t)mat * 65536, dyn);

    const int tid = threadIdx.x;
    const int te = tid & 7, to = tid >> 3;
    float bb[8];
#pragma unroll
    for (int j = 0; j < 8; j++) bb[j] = bias[to * 8 + j];

#pragma unroll
    for (int i = 0; i < 8; i++) {
        int rl = te * 8 + i;
        int row = row0 + rl;
        if (row < NN) {
            float4 e0 = es_ld(dyn, rl, to * 8);
            float4 e1 = es_ld(dyn, rl, to * 8 + 4);
            float* op = outp + (size_t)row * HC + to * 8;
            *(float4*)op = make_float4(e0.x + bb[0], e0.y + bb[1],
                                       e0.z + bb[2], e0.w + bb[3]);
            *(float4*)(op + 4) = make_float4(e1.x + bb[4], e1.y + bb[5],
                                             e1.z + bb[6], e1.w + bb[7]);
        }
    }
}

// ---------------------------------------------------------------------------
// Edge kernel over dst-SORTED edges: e = edge_attr[perm] @ We (fp16 HMMA)
// into Es, then fused attention with dst-run register reduction:
// warp w == head w; thread (te,tl) walks its 8 consecutive sorted edges,
// accumulating exp*(v+e) and exp in registers while dst is unchanged, and
// flushing one red.v4 pair + one den atomic per run. Q is loaded per run.
// ---------------------------------------------------------------------------
__global__ void __launch_bounds__(256, 2)
edge_kernel(const float* __restrict__ ea) {
    extern __shared__ char dyn[];
    __shared__ int s_src[64];
    __shared__ int s_dst[64];

    const int tid = threadIdx.x;
    const int row0 = blockIdx.x * 64;      // EE = 12500 * 64, no tail
    if (tid < 64) {
        s_src[tid] = g_src_s[row0 + tid];
        s_dst[tid] = g_dst_s[row0 + tid];
    }
    // visibility guaranteed by syncthreads inside gemm_hmma

    gemm_hmma(ea, row0, EE - 1, g_perm, g_Wimg + (size_t)4 * 65536, dyn);

    const int w  = tid >> 5;
    const int l  = tid & 31;
    const int te = tid & 7;
    const int tl = l >> 3;
    const int cbase = w * 32 + tl * 8;

    int cur = s_dst[te * 8];
    const float4* qp = (const float4*)(g_Q + (size_t)cur * HC + cbase);
    float4 q0 = qp[0], q1 = qp[1];
    float4 racc0 = make_float4(0.f, 0.f, 0.f, 0.f);
    float4 racc1 = make_float4(0.f, 0.f, 0.f, 0.f);
    float rden = 0.f;

#pragma unroll
    for (int i = 0; i < 8; i++) {
        const int eg  = te * 8 + i;
        const int dst = s_dst[eg];
        if (dst != cur) {
            float* op = g_acc + (size_t)cur * HC + cbase;
            red_add_v4(op, racc0);
            red_add_v4(op + 4, racc1);
            if (tl == 0) atomicAdd(g_den + (size_t)cur * HH + w, rden);
            racc0 = make_float4(0.f, 0.f, 0.f, 0.f);
            racc1 = make_float4(0.f, 0.f, 0.f, 0.f);
            rden = 0.f;
            cur = dst;
            qp = (const float4*)(g_Q + (size_t)cur * HC + cbase);
            q0 = qp[0]; q1 = qp[1];
        }
        const int src = s_src[eg];

        float4 e0 = es_ld(dyn, eg, cbase);
        float4 e1 = es_ld(dyn, eg, cbase + 4);

        const float4* kp = (const float4*)(g_K + (size_t)src * HC + cbase);
        float4 k0 = kp[0], k1 = kp[1];

        float p = (k0.x + e0.x) * q0.x + (k0.y + e0.y) * q0.y
                + (k0.z + e0.z) * q0.z + (k0.w + e0.w) * q0.w
                + (k1.x + e1.x) * q1.x + (k1.y + e1.y) * q1.y
                + (k1.z + e1.z) * q1.z + (k1.w + e1.w) * q1.w;

        // reduce over the 4 lanes holding this edge's head channels
        p += __shfl_xor_sync(0xffffffffu, p, 8);
        p += __shfl_xor_sync(0xffffffffu, p, 16);

        float exv = __expf(p * RSQRT_C);
        rden += exv;

        const float4* vp = (const float4*)(g_V + (size_t)src * HC + cbase);
        float4 v0 = vp[0], v1 = vp[1];
        racc0.x += exv * (v0.x + e0.x); racc0.y += exv * (v0.y + e0.y);
        racc0.z += exv * (v0.z + e0.z); racc0.w += exv * (v0.w + e0.w);
        racc1.x += exv * (v1.x + e1.x); racc1.y += exv * (v1.y + e1.y);
        racc1.z += exv * (v1.z + e1.z); racc1.w += exv * (v1.w + e1.w);
    }
    // final flush
    {
        float* op = g_acc + (size_t)cur * HC + cbase;
        red_add_v4(op, racc0);
        red_add_v4(op + 4, racc1);
        if (tl == 0) atomicAdd(g_den + (size_t)cur * HH + w, rden);
    }
}

// ---------------------------------------------------------------------------
// Finalize: out += acc / den
// ---------------------------------------------------------------------------
__global__ void finalize_kernel(float* __restrict__ out) {
    int idx = blockIdx.x * 256 + threadIdx.x;
    if (idx < NN * HC) {
        int n = idx >> 8;
        int h = (idx & 255) >> 5;
        float den = g_den[n * HH + h];
        float add = (den > 0.f) ? g_acc[idx] / den : 0.f;
        out[idx] += add;
    }
}

// ---------------------------------------------------------------------------
// Launch
// ---------------------------------------------------------------------------
extern "C" void kernel_launch(void* const* d_in, const int* in_sizes, int n_in,
                              void* d_out, int out_size) {
    (void)in_sizes; (void)n_in; (void)out_size;
    const float* x  = (const float*)d_in[0];
    const void*  ei = d_in[1];
    const float* ea = (const float*)d_in[2];
    const float* Wq = (const float*)d_in[3];
    const float* bq = (const float*)d_in[4];
    const float* Wk = (const float*)d_in[5];
    const float* bk = (const float*)d_in[6];
    const float* Wv = (const float*)d_in[7];
    const float* bv = (const float*)d_in[8];
    const float* We = (const float*)d_in[9];
    const float* Ws = (const float*)d_in[10];
    const float* bs = (const float*)d_in[11];
    float* out = (float*)d_out;

    cudaFuncSetAttribute(qkvs_kernel, cudaFuncAttributeMaxDynamicSharedMemorySize, DYN_BYTES);
    cudaFuncSetAttribute(edge_kernel, cudaFuncAttributeMaxDynamicSharedMemorySize, DYN_BYTES);

    detect_kernel<<<1, 32>>>((const int*)ei);
    extract_kernel<<<(EE + 255) / 256, 256>>>(ei);
    {
        int total = NN * HC + NN * HH + NN;
        zero_kernel<<<(total + 255) / 256, 256>>>();
    }
    hist_kernel<<<(EE + 255) / 256, 256>>>();
    scan_kernel<<<1, 1024>>>();
    scatter_kernel<<<(EE + 255) / 256, 256>>>();
    prep_kernel<<<(5 * 65536 + 255) / 256, 256>>>(Wq, Wk, Wv, Ws, We);
    {
        dim3 grid((NN + 63) / 64, 4);
        qkvs_kernel<<<grid, 256, DYN_BYTES>>>(x, bq, bk, bv, bs, out);
    }
    edge_kernel<<<EE / 64, 256, DYN_BYTES>>>(ea);
    finalize_kernel<<<(NN * HC + 255) / 256, 256>>>(out);
}